// round 5
// baseline (speedup 1.0000x reference)
#include <cuda_runtime.h>

// LIF_13984413516471  — B=128, S=128, H=128, K=8.
// s += x; spike = s > th[k]; out = spike ? s : 0; s -= out — serial over
// (i, j, k) per batch. Output: outs[b][i][k][j], spikes[b][i][k][j].
//
// A: chunk = one i-row (1024 substeps), spec sim from s=0; 8 chunks/warp,
//    smem-staged coalesced output; records spec end state.
// B: parallel verify+patch, ONE WARP PER CHUNK (full occupancy; heavy-tail
//    merge times don't serialize a warp). Candidate s_in = spec end of the
//    previous chunk; dual resim (spec vs candidate), patch diffs, early exit
//    at first co-spike (reset is to exact 0.0f -> bitwise-identical after).
// D: per-batch serial validity walk with vectorized all-ok fast exit;
//    off-spec chunks (rare) get an exact full rewrite resim.

#define BB 128
#define SS 128
#define HH 128
#define KK 8
#define NCHUNK (BB * SS)          // 16384
#define CPW 8                     // chunks per warp in kernel A
#define WPB 8                     // warps per block
#define QJ 16                     // j-steps per smem tile
#define NQ (HH / QJ)              // 8
#define CH_STRIDE (KK * QJ + 1)   // 129 floats: lane stride ≡ 1 mod 32

__device__ float g_spec_state[NCHUNK];
__device__ float g_end[NCHUNK];          // candidate-sim end (when no merge)
__device__ unsigned char g_ok[NCHUNK];   // candidate-sim end == spec end?

// ---------------------------------------------------------------- kernel A
__global__ __launch_bounds__(256) void lif_spec_kernel(
    const float* __restrict__ x, const float* __restrict__ th,
    float* __restrict__ outs, float* __restrict__ spikes, int write_spikes)
{
    __shared__ float buf[WPB][CPW * CH_STRIDE];   // 8 * 1032 * 4B = 33 KB

    const int w    = threadIdx.x >> 5;
    const int lane = threadIdx.x & 31;
    const int gw   = blockIdx.x * WPB + w;
    const int chunk0 = gw * CPW;

    float t[KK];
#pragma unroll
    for (int k = 0; k < KK; ++k) t[k] = __ldg(th + k);

    const bool active = lane < CPW;
    const int cl = active ? lane : 0;
    const float* __restrict__ xr = x + (size_t)(chunk0 + cl) * HH;
    float* bp = &buf[w][cl * CH_STRIDE];

    float s = 0.0f;

    for (int q = 0; q < NQ; ++q) {
        if (active) {
#pragma unroll
            for (int g = 0; g < QJ / 4; ++g) {
                float4 xv = *reinterpret_cast<const float4*>(xr + q * QJ + g * 4);
                float xa[4] = {xv.x, xv.y, xv.z, xv.w};
#pragma unroll
                for (int jj = 0; jj < 4; ++jj) {
                    float xx = xa[jj];
                    int j = g * 4 + jj;
#pragma unroll
                    for (int k = 0; k < KK; ++k) {
                        s += xx;
                        bool sp = s > t[k];
                        bp[k * QJ + j] = sp ? s : 0.0f;   // conflict-free STS
                        s = sp ? 0.0f : s;
                    }
                }
            }
        }
        __syncwarp();

        // Flush: 32 lanes cover 2 chunks x 16 j's per STG.
        {
            int jf = lane & 15;
            int ch = lane >> 4;
#pragma unroll
            for (int cp = 0; cp < CPW / 2; ++cp) {
                int c = cp * 2 + ch;
                size_t gbase = (size_t)(chunk0 + c) * (KK * HH) + q * QJ + jf;
                const float* sbf = &buf[w][c * CH_STRIDE + jf];
#pragma unroll
                for (int k = 0; k < KK; ++k) {
                    float v = sbf[k * QJ];
                    outs[gbase + k * HH] = v;
                    if (write_spikes)
                        spikes[gbase + k * HH] = v > 0.0f ? 1.0f : 0.0f;
                }
            }
        }
        __syncwarp();
    }

    if (active) g_spec_state[chunk0 + lane] = s;
}

// ---------------------------------------------------------------- kernel B
__global__ __launch_bounds__(256) void lif_verify_kernel(
    const float* __restrict__ x, const float* __restrict__ th,
    float* __restrict__ outs, float* __restrict__ spikes, int write_spikes)
{
    // one warp per chunk; all lanes compute redundantly (uniform branches)
    int chunk = (blockIdx.x * blockDim.x + threadIdx.x) >> 5;
    if (chunk >= NCHUNK) return;

    int i = chunk & (SS - 1);
    float sb = (i == 0) ? 0.0f : g_spec_state[chunk - 1];   // candidate s_in
    if (sb == 0.0f) { g_ok[chunk] = 1; return; }            // spec exact

    float t[KK];
#pragma unroll
    for (int k = 0; k < KK; ++k) t[k] = __ldg(th + k);

    const float4* __restrict__ xr4 =
        reinterpret_cast<const float4*>(x + (size_t)chunk * HH);
    float* orow = outs + (size_t)chunk * (KK * HH);
    float* srow = spikes + (size_t)chunk * (KK * HH);

    float sa = 0.0f;    // spec trajectory
    float4 cur = xr4[0];
    for (int g = 0; g < HH / 4; ++g) {
        float4 nxt = (g + 1 < HH / 4) ? xr4[g + 1] : cur;
        float xa[4] = {cur.x, cur.y, cur.z, cur.w};
#pragma unroll
        for (int jj = 0; jj < 4; ++jj) {
            float xx = xa[jj];
            int j = g * 4 + jj;
#pragma unroll
            for (int k = 0; k < KK; ++k) {
                sa += xx; sb += xx;
                bool spa = sa > t[k];
                bool spb = sb > t[k];
                int idx = k * HH + j;
                if (spa && spb) {
                    // co-spike: both reset to exact 0 -> identical afterward
                    orow[idx] = sb;          // all lanes same addr/value: 1 wf
                    g_ok[chunk] = 1;
                    return;
                }
                float ot = spb ? sb : 0.0f;
                float os = spa ? sa : 0.0f;
                if (ot != os) orow[idx] = ot;
                if (write_spikes && (spa != spb)) srow[idx] = spb ? 1.0f : 0.0f;
                sa = spa ? 0.0f : sa;
                sb = spb ? 0.0f : sb;
            }
        }
        cur = nxt;
    }
    // never merged: record candidate end; ok iff it coincides with spec end
    g_end[chunk] = sb;
    g_ok[chunk] = (sb == g_spec_state[chunk]) ? 1 : 0;
}

// ---------------------------------------------------------------- kernel D
__device__ void resim_full(const float* __restrict__ xrow,
                           const float* __restrict__ t, float& s,
                           float* __restrict__ orow, float* __restrict__ srow,
                           int write_spikes)
{
    const float4* xr4 = reinterpret_cast<const float4*>(xrow);
    for (int g = 0; g < HH / 4; ++g) {
        float4 xv = xr4[g];
        float xa[4] = {xv.x, xv.y, xv.z, xv.w};
#pragma unroll
        for (int jj = 0; jj < 4; ++jj) {
            float xx = xa[jj];
            int j = g * 4 + jj;
#pragma unroll
            for (int k = 0; k < KK; ++k) {
                s += xx;
                bool sp = s > t[k];
                float o = sp ? s : 0.0f;
                orow[k * HH + j] = o;
                if (write_spikes) srow[k * HH + j] = sp ? 1.0f : 0.0f;
                s = sp ? 0.0f : s;
            }
        }
    }
}

__global__ void lif_fix_kernel(
    const float* __restrict__ x, const float* __restrict__ th,
    float* __restrict__ outs, float* __restrict__ spikes, int write_spikes)
{
    if (threadIdx.x != 0) return;
    int b = blockIdx.x;
    int base = b * SS;

    // fast all-ok check: 128 flag bytes as 8 x uint4
    const uint4* okv = reinterpret_cast<const uint4*>(g_ok + base);
    unsigned int acc = 0x01010101u;
#pragma unroll
    for (int i = 0; i < 8; ++i) {
        uint4 v = okv[i];
        acc &= v.x & v.y & v.z & v.w;
    }
    if (acc == 0x01010101u) return;

    float t[KK];
#pragma unroll
    for (int k = 0; k < KK; ++k) t[k] = __ldg(th + k);

    float s = 0.0f;
    bool on_spec = true;   // true end of previous chunk == its spec end
    for (int i = 1; i < SS; ++i) {
        int c = base + i;
        if (on_spec) {
            if (g_ok[c]) continue;
            // candidate s_in was correct; B's patch of chunk c is valid,
            // but its true end diverges from spec: go off-spec.
            s = g_end[c];
            on_spec = false;
            continue;
        }
        // off-spec: s = true end of chunk c-1 (!= spec). Full exact rewrite.
        resim_full(x + (size_t)c * HH, t, s,
                   outs + (size_t)c * (KK * HH),
                   spikes + (size_t)c * (KK * HH), write_spikes);
        if (s == g_spec_state[c]) on_spec = true;
    }
}

extern "C" void kernel_launch(void* const* d_in, const int* in_sizes, int n_in,
                              void* d_out, int out_size) {
    const float* x  = (const float*)d_in[0];   // (B, S, H) f32
    const float* th = (const float*)d_in[1];   // (K,) f32
    float* outs = (float*)d_out;

    const long long N = (long long)BB * SS * KK * HH;   // 16777216
    int write_spikes = ((long long)out_size >= 2 * N) ? 1 : 0;
    float* spikes = outs + N;

    lif_spec_kernel<<<NCHUNK / (CPW * WPB), WPB * 32>>>(x, th, outs, spikes,
                                                        write_spikes);
    lif_verify_kernel<<<(NCHUNK * 32) / 256, 256>>>(x, th, outs, spikes,
                                                    write_spikes);
    lif_fix_kernel<<<BB, 32>>>(x, th, outs, spikes, write_spikes);
}

// round 6
// speedup vs baseline: 5.7836x; 5.7836x over previous
#include <cuda_runtime.h>
#include <math_constants.h>

// LIF_13984413516471  — B=128, S=128, H=128, K=8.
// s += x; spike = s > th[k]; out = spike ? s : 0; s -= out — serial over
// (i, j, k) per batch. Output: outs[b][i][k][j], spikes[b][i][k][j].
//
// A: chunk = one i-row (1024 substeps), spec sim from s=0; smem-staged
//    coalesced output. Also: spec end state, chunk sum S, silence bound M
//    (safe upper bound on max_t(prefix_t - th)).
// B: one WARP per batch; state-only walk with O(1) fast paths:
//    s==0 -> spec end (exact); s <= -(M+0.01) -> s += S (provably silent);
//    else dual resim w/ early exit at co-spike (snaps to bitwise spec end).
//    Metadata prefetched to smem. Records true s_in per chunk.
// C: one warp per chunk, parallel patch: skip (s_in==0) / zero-fill (silent)
//    / dual-resim diff-patch with early exit at co-spike.

#define BB 128
#define SS 128
#define HH 128
#define KK 8
#define NCHUNK (BB * SS)          // 16384
#define CPW 8
#define WPB 8
#define QJ 16
#define NQ (HH / QJ)
#define CH_STRIDE (KK * QJ + 1)   // 129

#define MARGIN 0.01f

__device__ float g_spec_state[NCHUNK];
__device__ float g_S[NCHUNK];        // chunk total sum (per-j jumps; ~eps off seq)
__device__ float g_M[NCHUNK];        // >= max_t(prefix_t - th_t)  (safe bound)
__device__ float g_true_in[NCHUNK];  // true state entering each chunk

// ---------------------------------------------------------------- kernel A
__global__ __launch_bounds__(256) void lif_spec_kernel(
    const float* __restrict__ x, const float* __restrict__ th,
    float* __restrict__ outs, float* __restrict__ spikes, int write_spikes)
{
    __shared__ float buf[WPB][CPW * CH_STRIDE];

    const int w    = threadIdx.x >> 5;
    const int lane = threadIdx.x & 31;
    const int gw   = blockIdx.x * WPB + w;
    const int chunk0 = gw * CPW;

    float t[KK];
    float tmin = CUDART_INF_F;
#pragma unroll
    for (int k = 0; k < KK; ++k) { t[k] = __ldg(th + k); tmin = fminf(tmin, t[k]); }

    const bool active = lane < CPW;
    const int cl = active ? lane : 0;
    const float* __restrict__ xr = x + (size_t)(chunk0 + cl) * HH;
    float* bp = &buf[w][cl * CH_STRIDE];

    float s = 0.0f;
    float p = 0.0f;                  // per-j jumped prefix (for S and M bound)
    float Mp = -CUDART_INF_F;        // max over j of (p_before_j + max(8x, x))

    for (int q = 0; q < NQ; ++q) {
        if (active) {
#pragma unroll
            for (int g = 0; g < QJ / 4; ++g) {
                float4 xv = *reinterpret_cast<const float4*>(xr + q * QJ + g * 4);
                float xa[4] = {xv.x, xv.y, xv.z, xv.w};
#pragma unroll
                for (int jj = 0; jj < 4; ++jj) {
                    float xx = xa[jj];
                    int j = g * 4 + jj;
                    // silence-bound bookkeeping (cheap, per j)
                    float e8 = 8.0f * xx;
                    Mp = fmaxf(Mp, p + fmaxf(e8, xx));
                    p += e8;
#pragma unroll
                    for (int k = 0; k < KK; ++k) {
                        s += xx;
                        bool sp = s > t[k];
                        bp[k * QJ + j] = sp ? s : 0.0f;
                        s = sp ? 0.0f : s;
                    }
                }
            }
        }
        __syncwarp();
        {
            int jf = lane & 15;
            int ch = lane >> 4;
#pragma unroll
            for (int cp = 0; cp < CPW / 2; ++cp) {
                int c = cp * 2 + ch;
                size_t gbase = (size_t)(chunk0 + c) * (KK * HH) + q * QJ + jf;
                const float* sbf = &buf[w][c * CH_STRIDE + jf];
#pragma unroll
                for (int k = 0; k < KK; ++k) {
                    float v = sbf[k * QJ];
                    outs[gbase + k * HH] = v;
                    if (write_spikes)
                        spikes[gbase + k * HH] = v > 0.0f ? 1.0f : 0.0f;
                }
            }
        }
        __syncwarp();
    }

    if (active) {
        g_spec_state[chunk0 + lane] = s;
        g_S[chunk0 + lane] = p;
        g_M[chunk0 + lane] = Mp - tmin;   // prefix - th <= prefix - tmin <= Mp - tmin
    }
}

// ---------------------------------------------------------------- kernel B
__global__ __launch_bounds__(32) void lif_state_kernel(
    const float* __restrict__ x, const float* __restrict__ th)
{
    __shared__ float smM[SS], smS[SS], smE[SS];

    const int b = blockIdx.x;
    const int lane = threadIdx.x;
    const int base = b * SS;

    // warp-cooperative metadata prefetch (coalesced)
#pragma unroll
    for (int r = 0; r < SS / 32; ++r) {
        int i = r * 32 + lane;
        smM[i] = g_M[base + i];
        smS[i] = g_S[base + i];
        smE[i] = g_spec_state[base + i];
    }
    __syncwarp();

    float t[KK];
#pragma unroll
    for (int k = 0; k < KK; ++k) t[k] = __ldg(th + k);

    float s = 0.0f;
    for (int i = 0; i < SS; ++i) {
        if (lane == 0) g_true_in[base + i] = s;

        if (s == 0.0f) { s = smE[i]; continue; }                 // exact
        if (s <= -(smM[i] + MARGIN)) { s += smS[i]; continue; }  // silent

        // dual resim (all lanes redundant, uniform): early exit at co-spike
        const float4* __restrict__ xr4 =
            reinterpret_cast<const float4*>(x + (size_t)(base + i) * HH);
        float sa = 0.0f, sb = s;
        bool merged = false;
        float4 cur = xr4[0];
        for (int g = 0; g < HH / 4; ++g) {
            float4 nxt = (g + 1 < HH / 4) ? xr4[g + 1] : cur;
            float xa[4] = {cur.x, cur.y, cur.z, cur.w};
            bool co = false;
#pragma unroll
            for (int jj = 0; jj < 4; ++jj) {
                float xx = xa[jj];
#pragma unroll
                for (int k = 0; k < KK; ++k) {
                    sa += xx; sb += xx;
                    bool spa = sa > t[k];
                    bool spb = sb > t[k];
                    co = co || (spa && spb);
                    sa = spa ? 0.0f : sa;
                    sb = spb ? 0.0f : sb;
                }
            }
            cur = nxt;
            if (co) { merged = true; break; }
        }
        s = merged ? smE[i] : sb;
    }
}

// ---------------------------------------------------------------- kernel C
__global__ __launch_bounds__(256) void lif_patch_kernel(
    const float* __restrict__ x, const float* __restrict__ th,
    float* __restrict__ outs, float* __restrict__ spikes, int write_spikes)
{
    int chunk = (blockIdx.x * blockDim.x + threadIdx.x) >> 5;
    int lane  = threadIdx.x & 31;
    if (chunk >= NCHUNK) return;

    float sb = g_true_in[chunk];
    if (sb == 0.0f) return;                    // spec outputs already exact

    float* orow = outs + (size_t)chunk * (KK * HH);
    float* srow = spikes + (size_t)chunk * (KK * HH);

    if (sb <= -(g_M[chunk] + MARGIN)) {
        // silent: out = 0, spikes = 0 for the whole chunk (coalesced)
        float4 z = make_float4(0.f, 0.f, 0.f, 0.f);
        float4* o4 = reinterpret_cast<float4*>(orow);
        float4* s4 = reinterpret_cast<float4*>(srow);
#pragma unroll
        for (int it = 0; it < (KK * HH / 4) / 32; ++it) {
            o4[it * 32 + lane] = z;
            if (write_spikes) s4[it * 32 + lane] = z;
        }
        return;
    }

    float t[KK];
#pragma unroll
    for (int k = 0; k < KK; ++k) t[k] = __ldg(th + k);

    const float4* __restrict__ xr4 =
        reinterpret_cast<const float4*>(x + (size_t)chunk * HH);

    float sa = 0.0f;   // spec trajectory (matches what A wrote)
    float4 cur = xr4[0];
    for (int g = 0; g < HH / 4; ++g) {
        float4 nxt = (g + 1 < HH / 4) ? xr4[g + 1] : cur;
        float xa[4] = {cur.x, cur.y, cur.z, cur.w};
#pragma unroll
        for (int jj = 0; jj < 4; ++jj) {
            float xx = xa[jj];
            int j = g * 4 + jj;
#pragma unroll
            for (int k = 0; k < KK; ++k) {
                sa += xx; sb += xx;
                bool spa = sa > t[k];
                bool spb = sb > t[k];
                int idx = k * HH + j;
                if (spa && spb) {
                    // co-spike: identical to spec afterward; patch value only
                    orow[idx] = sb;
                    return;
                }
                float ot = spb ? sb : 0.0f;
                float os = spa ? sa : 0.0f;
                if (ot != os) orow[idx] = ot;
                if (write_spikes && (spa != spb)) srow[idx] = spb ? 1.0f : 0.0f;
                sa = spa ? 0.0f : sa;
                sb = spb ? 0.0f : sb;
            }
        }
        cur = nxt;
    }
}

extern "C" void kernel_launch(void* const* d_in, const int* in_sizes, int n_in,
                              void* d_out, int out_size) {
    const float* x  = (const float*)d_in[0];   // (B, S, H) f32
    const float* th = (const float*)d_in[1];   // (K,) f32
    float* outs = (float*)d_out;

    const long long N = (long long)BB * SS * KK * HH;   // 16777216
    int write_spikes = ((long long)out_size >= 2 * N) ? 1 : 0;
    float* spikes = outs + N;

    lif_spec_kernel<<<NCHUNK / (CPW * WPB), WPB * 32>>>(x, th, outs, spikes,
                                                        write_spikes);
    lif_state_kernel<<<BB, 32>>>(x, th);
    lif_patch_kernel<<<(NCHUNK * 32) / 256, 256>>>(x, th, outs, spikes,
                                                   write_spikes);
}

// round 8
// speedup vs baseline: 8.9354x; 1.5450x over previous
#include <cuda_runtime.h>
#include <math_constants.h>

// LIF_13984413516471  — B=128, S=128, H=128, K=8.
// s += x; spike = s > th[k]; out = spike ? s : 0; s -= out — serial (i,j,k).
// Output: outs[b][i][k][j], spikes[b][i][k][j].
//
// A : spec sim per chunk (one i-row, 1024 substeps) from s=0; smem-staged
//     coalesced output; metadata: spec end E, chunk sum S, silence bound M.
// B1: warp/batch O(1)-per-chunk state walk, NO x access:
//     s==0 -> exact (cls 0);  s <= -(M+m) -> silent jump (cls 1);
//     else ASSUME co-spike merge: s -> E (cls 2).
// V : warp/chunk: cls1 -> zero-fill; cls2 -> dual resim from recorded s_in,
//     patch diffs, early-exit at co-spike; no merge -> bad flag + true end.
// R : warp/batch: no bad -> exit; else rewrite from first bad chunk until
//     state resyncs with B1's recorded chain.

#define BB 128
#define SS 128
#define HH 128
#define KK 8
#define NCHUNK (BB * SS)          // 16384
#define CPW 16                    // chunks per warp in A
#define WPB 4                     // warps per block in A
#define QJ 8                      // j-steps per smem tile
#define NQ (HH / QJ)              // 16
#define CH_STRIDE (KK * QJ + 1)   // 65: lane stride ≡ 1 mod 32 (conflict-free)
#define MARGIN 0.01f

__device__ float g_E[NCHUNK];          // spec end state
__device__ float g_S[NCHUNK];          // chunk sum (per-j jumps)
__device__ float g_M[NCHUNK];          // >= max_t(prefix_t - th_t) (safe bound)
__device__ float g_in[NCHUNK];         // B1 state entering chunk
__device__ float g_endv[NCHUNK];       // V: true end when not merged
__device__ unsigned char g_cls[NCHUNK];
__device__ unsigned char g_bad[NCHUNK];

// ---------------------------------------------------------------- kernel A
__global__ __launch_bounds__(128) void lif_spec_kernel(
    const float* __restrict__ x, const float* __restrict__ th,
    float* __restrict__ outs, float* __restrict__ spikes, int write_spikes)
{
    __shared__ float buf[WPB][CPW * CH_STRIDE];   // 4 * 1040 * 4B ≈ 16.6 KB

    const int w    = threadIdx.x >> 5;
    const int lane = threadIdx.x & 31;
    const int gw   = blockIdx.x * WPB + w;
    const int chunk0 = gw * CPW;

    float t[KK];
    float tmin = CUDART_INF_F;
#pragma unroll
    for (int k = 0; k < KK; ++k) { t[k] = __ldg(th + k); tmin = fminf(tmin, t[k]); }

    const bool active = lane < CPW;
    const int cl = active ? lane : 0;
    const float* __restrict__ xr = x + (size_t)(chunk0 + cl) * HH;
    float* bp = &buf[w][cl * CH_STRIDE];

    float s = 0.0f;
    float p = 0.0f;                  // per-j jumped prefix
    float Mp = -CUDART_INF_F;

    for (int q = 0; q < NQ; ++q) {
        if (active) {
#pragma unroll
            for (int g = 0; g < QJ / 4; ++g) {
                float4 xv = *reinterpret_cast<const float4*>(xr + q * QJ + g * 4);
                float xa[4] = {xv.x, xv.y, xv.z, xv.w};
#pragma unroll
                for (int jj = 0; jj < 4; ++jj) {
                    float xx = xa[jj];
                    int j = g * 4 + jj;
                    float e8 = 8.0f * xx;
                    Mp = fmaxf(Mp, p + fmaxf(e8, xx));
                    p += e8;
#pragma unroll
                    for (int k = 0; k < KK; ++k) {
                        s += xx;
                        bool sp = s > t[k];
                        bp[k * QJ + j] = sp ? s : 0.0f;
                        s = sp ? 0.0f : s;
                    }
                }
            }
        }
        __syncwarp();
        {
            int jf = lane & 7;
            int ch = lane >> 3;                      // 0..3
#pragma unroll
            for (int cp = 0; cp < CPW / 4; ++cp) {
                int c = cp * 4 + ch;
                size_t gbase = (size_t)(chunk0 + c) * (KK * HH) + q * QJ + jf;
                const float* sbf = &buf[w][c * CH_STRIDE + jf];
#pragma unroll
                for (int k = 0; k < KK; ++k) {
                    float v = sbf[k * QJ];
                    outs[gbase + k * HH] = v;
                    if (write_spikes)
                        spikes[gbase + k * HH] = v > 0.0f ? 1.0f : 0.0f;
                }
            }
        }
        __syncwarp();
    }

    if (active) {
        g_E[chunk0 + lane] = s;
        g_S[chunk0 + lane] = p;
        g_M[chunk0 + lane] = Mp - tmin;
    }
}

// ---------------------------------------------------------------- kernel B1
__global__ __launch_bounds__(32) void lif_state_kernel()
{
    __shared__ float smM[SS], smS[SS], smE[SS];
    const int b = blockIdx.x, lane = threadIdx.x, base = b * SS;

#pragma unroll
    for (int r = 0; r < SS / 32; ++r) {
        int i = r * 32 + lane;
        smM[i] = g_M[base + i];
        smS[i] = g_S[base + i];
        smE[i] = g_E[base + i];
    }
    __syncwarp();
    if (lane != 0) return;

    float s = 0.0f;
    for (int i = 0; i < SS; ++i) {
        int c = base + i;
        g_in[c] = s;
        g_bad[c] = 0;
        if (s == 0.0f)                      { g_cls[c] = 0; s = smE[i]; }
        else if (s <= -(smM[i] + MARGIN))   { g_cls[c] = 1; s += smS[i]; }
        else                                { g_cls[c] = 2; s = smE[i]; }  // assume merge
    }
}

// ---------------------------------------------------------------- kernel V
__global__ __launch_bounds__(256) void lif_verify_kernel(
    const float* __restrict__ x, const float* __restrict__ th,
    float* __restrict__ outs, float* __restrict__ spikes, int write_spikes)
{
    int chunk = (blockIdx.x * blockDim.x + threadIdx.x) >> 5;
    int lane  = threadIdx.x & 31;
    if (chunk >= NCHUNK) return;

    unsigned char cls = g_cls[chunk];
    if (cls == 0) return;                       // spec outputs already exact

    float* orow = outs + (size_t)chunk * (KK * HH);
    float* srow = spikes + (size_t)chunk * (KK * HH);

    if (cls == 1) {                             // silent: zero-fill (coalesced)
        float4 z = make_float4(0.f, 0.f, 0.f, 0.f);
        float4* o4 = reinterpret_cast<float4*>(orow);
        float4* s4 = reinterpret_cast<float4*>(srow);
#pragma unroll
        for (int it = 0; it < (KK * HH / 4) / 32; ++it) {
            o4[it * 32 + lane] = z;
            if (write_spikes) s4[it * 32 + lane] = z;
        }
        return;
    }

    // cls == 2: dual resim from recorded s_in; verify the merge assumption.
    float t[KK];
#pragma unroll
    for (int k = 0; k < KK; ++k) t[k] = __ldg(th + k);

    const float4* __restrict__ xr4 =
        reinterpret_cast<const float4*>(x + (size_t)chunk * HH);
    float sa = 0.0f;                    // spec trajectory (what A wrote)
    float sb = g_in[chunk];             // candidate-true trajectory

    float4 cur = xr4[0];
    for (int g = 0; g < HH / 4; ++g) {
        float4 nxt = (g + 1 < HH / 4) ? xr4[g + 1] : cur;
        float xa[4] = {cur.x, cur.y, cur.z, cur.w};
#pragma unroll
        for (int jj = 0; jj < 4; ++jj) {
            float xx = xa[jj];
            int j = g * 4 + jj;
#pragma unroll
            for (int k = 0; k < KK; ++k) {
                sa += xx; sb += xx;
                bool spa = sa > t[k];
                bool spb = sb > t[k];
                int idx = k * HH + j;
                if (spa && spb) {
                    // co-spike: both reset to exact 0 -> identical afterward;
                    // merge assumption verified. Patch value only.
                    orow[idx] = sb;
                    return;
                }
                float ot = spb ? sb : 0.0f;
                float os = spa ? sa : 0.0f;
                if (ot != os) orow[idx] = ot;
                if (write_spikes && (spa != spb)) srow[idx] = spb ? 1.0f : 0.0f;
                sa = spa ? 0.0f : sa;
                sb = spb ? 0.0f : sb;
            }
        }
        cur = nxt;
    }
    // never merged: assumption wrong downstream; record true end.
    if (lane == 0) { g_endv[chunk] = sb; g_bad[chunk] = 1; }
}

// ---------------------------------------------------------------- kernel R
__device__ void resim_full(const float* __restrict__ xrow,
                           const float* __restrict__ t, float& s,
                           float* __restrict__ orow, float* __restrict__ srow,
                           int write_spikes)
{
    const float4* xr4 = reinterpret_cast<const float4*>(xrow);
    for (int g = 0; g < HH / 4; ++g) {
        float4 xv = xr4[g];
        float xa[4] = {xv.x, xv.y, xv.z, xv.w};
#pragma unroll
        for (int jj = 0; jj < 4; ++jj) {
            float xx = xa[jj];
            int j = g * 4 + jj;
#pragma unroll
            for (int k = 0; k < KK; ++k) {
                s += xx;
                bool sp = s > t[k];
                float o = sp ? s : 0.0f;
                orow[k * HH + j] = o;
                if (write_spikes) srow[k * HH + j] = sp ? 1.0f : 0.0f;
                s = sp ? 0.0f : s;
            }
        }
    }
}

__device__ __forceinline__ bool resynced(float s, float ref) {
    return fabsf(s - ref) <= 1e-3f * fmaxf(1.0f, fabsf(s));
}

__global__ __launch_bounds__(32) void lif_repair_kernel(
    const float* __restrict__ x, const float* __restrict__ th,
    float* __restrict__ outs, float* __restrict__ spikes, int write_spikes)
{
    const int b = blockIdx.x, lane = threadIdx.x, base = b * SS;

    // fast scan for first bad chunk (4 flag bytes per lane)
    unsigned int word = reinterpret_cast<const unsigned int*>(g_bad + base)[lane];
    unsigned int ballot = __ballot_sync(0xFFFFFFFFu, word != 0u);
    if (!ballot) return;
    int fl = __ffs(ballot) - 1;
    unsigned int wv = __shfl_sync(0xFFFFFFFFu, word, fl);
    int byte = 0;
    while (((wv >> (byte * 8)) & 0xFFu) == 0u) ++byte;
    int i0 = fl * 4 + byte;

    float t[KK];
#pragma unroll
    for (int k = 0; k < KK; ++k) t[k] = __ldg(th + k);

    // chunk i0: s_in was correct (first bad), V's patch valid; true end known.
    float s = g_endv[base + i0];
    int i = i0 + 1;
    while (i < SS) {
        int c = base + i;
        if (resynced(s, g_in[c])) {
            if (g_bad[c]) { s = g_endv[c]; ++i; continue; }   // patch valid; end diverges
            // chain in sync & chunk not bad -> correct until next bad chunk
            ++i;
            while (i < SS && !g_bad[base + i]) ++i;
            if (i >= SS) return;
            s = g_endv[base + i];                             // its s_in was in sync
            ++i;
            continue;
        }
        // off-chain: exact full rewrite of chunk c (all lanes uniform)
        resim_full(x + (size_t)c * HH, t, s,
                   outs + (size_t)c * (KK * HH),
                   spikes + (size_t)c * (KK * HH), write_spikes);
        ++i;
    }
}

extern "C" void kernel_launch(void* const* d_in, const int* in_sizes, int n_in,
                              void* d_out, int out_size) {
    const float* x  = (const float*)d_in[0];   // (B, S, H) f32
    const float* th = (const float*)d_in[1];   // (K,) f32
    float* outs = (float*)d_out;

    const long long N = (long long)BB * SS * KK * HH;   // 16777216
    int write_spikes = ((long long)out_size >= 2 * N) ? 1 : 0;
    float* spikes = outs + N;

    lif_spec_kernel<<<NCHUNK / (CPW * WPB), WPB * 32>>>(x, th, outs, spikes,
                                                        write_spikes);
    lif_state_kernel<<<BB, 32>>>();
    lif_verify_kernel<<<(NCHUNK * 32) / 256, 256>>>(x, th, outs, spikes,
                                                    write_spikes);
    lif_repair_kernel<<<BB, 32>>>(x, th, outs, spikes, write_spikes);
}

// round 10
// speedup vs baseline: 12.2584x; 1.3719x over previous
#include <cuda_runtime.h>
#include <math_constants.h>

// LIF_13984413516471  — B=128, S=128, H=128, K=8.
// s += x; spike = s > th[k]; out = spike ? s : 0; s -= out — serial (i,j,k).
// Output: outs[b][i][k][j], spikes[b][i][k][j].
//
// A : spec sim per chunk (one i-row, 1024 substeps) from s=0; smem-staged
//     coalesced output; metadata: spec end E, chunk sum S, silence bound M.
// B1: warp/batch O(1)-per-chunk state walk (no x): cls0 s==0 exact;
//     cls1 silent jump; cls2 assume co-spike merge (s -> E).
// V : warp/chunk: cls1 zero-fill; cls2 dual resim from g_in, diff-patch,
//     early exit at co-spike; no merge -> bad flag + true end g_endv.
//     INVARIANT after V: memory of chunk c == outputs of trajectory from
//     g_in[c] (cls0 spec, cls1 zeros, cls2 g_in-trajectory).
// R : warp/batch repair using the invariant: off-chain silent -> zero-fill
//     (only if cls!=1) + O(1) jump; off-chain active -> dual resim vs the
//     g_in-trajectory with early exit (memory already right past co-spike);
//     exact bitwise chain-return; on-chain -> skip to next bad chunk.

#define BB 128
#define SS 128
#define HH 128
#define KK 8
#define NCHUNK (BB * SS)          // 16384
#define CPW 16                    // chunks per warp in A
#define WPB 4                     // warps per block in A
#define QJ 8                      // j-steps per smem tile
#define NQ (HH / QJ)              // 16
#define CH_STRIDE (KK * QJ + 1)   // 65: lane stride ≡ 1 mod 32 (conflict-free)
#define MARGIN 0.01f

__device__ float g_E[NCHUNK];          // spec end state
__device__ float g_S[NCHUNK];          // chunk sum (per-j jumps)
__device__ float g_M[NCHUNK];          // >= max_t(prefix_t - th_t) (safe bound)
__device__ float g_in[NCHUNK];         // B1 state entering chunk
__device__ float g_endv[NCHUNK];       // V: true end when not merged
__device__ unsigned char g_cls[NCHUNK];
__device__ unsigned char g_bad[NCHUNK];

// ---------------------------------------------------------------- kernel A
__global__ __launch_bounds__(128) void lif_spec_kernel(
    const float* __restrict__ x, const float* __restrict__ th,
    float* __restrict__ outs, float* __restrict__ spikes, int write_spikes)
{
    __shared__ float buf[WPB][CPW * CH_STRIDE];   // ≈ 16.6 KB

    const int w    = threadIdx.x >> 5;
    const int lane = threadIdx.x & 31;
    const int gw   = blockIdx.x * WPB + w;
    const int chunk0 = gw * CPW;

    float t[KK];
    float tmin = CUDART_INF_F;
#pragma unroll
    for (int k = 0; k < KK; ++k) { t[k] = __ldg(th + k); tmin = fminf(tmin, t[k]); }

    const bool active = lane < CPW;
    const int cl = active ? lane : 0;
    const float* __restrict__ xr = x + (size_t)(chunk0 + cl) * HH;
    float* bp = &buf[w][cl * CH_STRIDE];

    float s = 0.0f;
    float p = 0.0f;                  // per-j jumped prefix
    float Mp = -CUDART_INF_F;

    for (int q = 0; q < NQ; ++q) {
        if (active) {
#pragma unroll
            for (int g = 0; g < QJ / 4; ++g) {
                float4 xv = *reinterpret_cast<const float4*>(xr + q * QJ + g * 4);
                float xa[4] = {xv.x, xv.y, xv.z, xv.w};
#pragma unroll
                for (int jj = 0; jj < 4; ++jj) {
                    float xx = xa[jj];
                    int j = g * 4 + jj;
                    float e8 = 8.0f * xx;
                    Mp = fmaxf(Mp, p + fmaxf(e8, xx));
                    p += e8;
#pragma unroll
                    for (int k = 0; k < KK; ++k) {
                        s += xx;
                        bool sp = s > t[k];
                        bp[k * QJ + j] = sp ? s : 0.0f;
                        s = sp ? 0.0f : s;
                    }
                }
            }
        }
        __syncwarp();
        {
            int jf = lane & 7;
            int ch = lane >> 3;                      // 0..3
#pragma unroll
            for (int cp = 0; cp < CPW / 4; ++cp) {
                int c = cp * 4 + ch;
                size_t gbase = (size_t)(chunk0 + c) * (KK * HH) + q * QJ + jf;
                const float* sbf = &buf[w][c * CH_STRIDE + jf];
#pragma unroll
                for (int k = 0; k < KK; ++k) {
                    float v = sbf[k * QJ];
                    outs[gbase + k * HH] = v;
                    if (write_spikes)
                        spikes[gbase + k * HH] = v > 0.0f ? 1.0f : 0.0f;
                }
            }
        }
        __syncwarp();
    }

    if (active) {
        g_E[chunk0 + lane] = s;
        g_S[chunk0 + lane] = p;
        g_M[chunk0 + lane] = Mp - tmin;
    }
}

// ---------------------------------------------------------------- kernel B1
__global__ __launch_bounds__(32) void lif_state_kernel()
{
    __shared__ float smM[SS], smS[SS], smE[SS];
    const int b = blockIdx.x, lane = threadIdx.x, base = b * SS;

#pragma unroll
    for (int r = 0; r < SS / 32; ++r) {
        int i = r * 32 + lane;
        smM[i] = g_M[base + i];
        smS[i] = g_S[base + i];
        smE[i] = g_E[base + i];
    }
    __syncwarp();
    if (lane != 0) return;

    float s = 0.0f;
    for (int i = 0; i < SS; ++i) {
        int c = base + i;
        g_in[c] = s;
        g_bad[c] = 0;
        if (s == 0.0f)                      { g_cls[c] = 0; s = smE[i]; }
        else if (s <= -(smM[i] + MARGIN))   { g_cls[c] = 1; s += smS[i]; }
        else                                { g_cls[c] = 2; s = smE[i]; }  // assume merge
    }
}

// --------------------------------------------------------- shared dual resim
// Resim trajectory-b (start sb) against trajectory-a (start sa == what the
// chunk's memory currently holds). Diff-patch; early exit at co-spike (both
// reset to exact 0 -> identical afterward; memory already correct beyond).
// Returns true if merged; otherwise *end_out = final sb.
__device__ __forceinline__ bool dual_patch(
    const float* __restrict__ xrow, const float* __restrict__ t,
    float sa, float sb, float* __restrict__ orow, float* __restrict__ srow,
    int write_spikes, float* end_out)
{
    const float4* __restrict__ xr4 = reinterpret_cast<const float4*>(xrow);
    float4 cur = xr4[0];
    for (int g = 0; g < HH / 4; ++g) {
        float4 nxt = (g + 1 < HH / 4) ? xr4[g + 1] : cur;
        float xa[4] = {cur.x, cur.y, cur.z, cur.w};
#pragma unroll
        for (int jj = 0; jj < 4; ++jj) {
            float xx = xa[jj];
            int j = g * 4 + jj;
#pragma unroll
            for (int k = 0; k < KK; ++k) {
                sa += xx; sb += xx;
                bool spa = sa > t[k];
                bool spb = sb > t[k];
                int idx = k * HH + j;
                if (spa && spb) { orow[idx] = sb; return true; }
                float ot = spb ? sb : 0.0f;
                float os = spa ? sa : 0.0f;
                if (ot != os) orow[idx] = ot;
                if (write_spikes && (spa != spb)) srow[idx] = spb ? 1.0f : 0.0f;
                sa = spa ? 0.0f : sa;
                sb = spb ? 0.0f : sb;
            }
        }
        cur = nxt;
    }
    *end_out = sb;
    return false;
}

// ---------------------------------------------------------------- kernel V
__global__ __launch_bounds__(256) void lif_verify_kernel(
    const float* __restrict__ x, const float* __restrict__ th,
    float* __restrict__ outs, float* __restrict__ spikes, int write_spikes)
{
    int chunk = (blockIdx.x * blockDim.x + threadIdx.x) >> 5;
    int lane  = threadIdx.x & 31;
    if (chunk >= NCHUNK) return;

    unsigned char cls = g_cls[chunk];
    if (cls == 0) return;                       // spec outputs already exact

    float* orow = outs + (size_t)chunk * (KK * HH);
    float* srow = spikes + (size_t)chunk * (KK * HH);

    if (cls == 1) {                             // silent: zero-fill (coalesced)
        float4 z = make_float4(0.f, 0.f, 0.f, 0.f);
        float4* o4 = reinterpret_cast<float4*>(orow);
        float4* s4 = reinterpret_cast<float4*>(srow);
#pragma unroll
        for (int it = 0; it < (KK * HH / 4) / 32; ++it) {
            o4[it * 32 + lane] = z;
            if (write_spikes) s4[it * 32 + lane] = z;
        }
        return;
    }

    // cls == 2: dual resim from recorded s_in vs spec (memory = spec).
    float t[KK];
#pragma unroll
    for (int k = 0; k < KK; ++k) t[k] = __ldg(th + k);

    float endv;
    bool merged = dual_patch(x + (size_t)chunk * HH, t, 0.0f, g_in[chunk],
                             orow, srow, write_spikes, &endv);
    if (!merged && lane == 0) { g_endv[chunk] = endv; g_bad[chunk] = 1; }
}

// ---------------------------------------------------------------- kernel R
__global__ __launch_bounds__(32) void lif_repair_kernel(
    const float* __restrict__ x, const float* __restrict__ th,
    float* __restrict__ outs, float* __restrict__ spikes, int write_spikes)
{
    __shared__ float smIn[SS], smE[SS], smS[SS], smM[SS], smEndv[SS];
    __shared__ unsigned char smBad[SS], smCls[SS];

    const int b = blockIdx.x, lane = threadIdx.x, base = b * SS;

    // fast no-bad exit (4 flag bytes per lane)
    unsigned int word = reinterpret_cast<const unsigned int*>(g_bad + base)[lane];
    unsigned int ballot = __ballot_sync(0xFFFFFFFFu, word != 0u);
    if (!ballot) return;

    // cooperative metadata prefetch
#pragma unroll
    for (int r = 0; r < SS / 32; ++r) {
        int i = r * 32 + lane;
        smIn[i]   = g_in[base + i];
        smE[i]    = g_E[base + i];
        smS[i]    = g_S[base + i];
        smM[i]    = g_M[base + i];
        smEndv[i] = g_endv[base + i];
        smBad[i]  = g_bad[base + i];
        smCls[i]  = g_cls[base + i];
    }
    __syncwarp();

    float t[KK];
#pragma unroll
    for (int k = 0; k < KK; ++k) t[k] = __ldg(th + k);

    // first bad chunk: its s_in (B1 chain) was correct, V patch valid.
    int i = 0;
    while (i < SS && !smBad[i]) ++i;
    if (i >= SS) return;
    float s = smEndv[i];
    ++i;

    while (i < SS) {
        // exact bitwise chain-return test
        if (s == smIn[i]) {
            // on chain: everything valid until next bad chunk
            while (i < SS && !smBad[i]) ++i;
            if (i >= SS) return;
            s = smEndv[i];          // its s_in was on-chain -> patch valid
            ++i;
            continue;
        }

        int c = base + i;
        float* orow = outs + (size_t)c * (KK * HH);
        float* srow = spikes + (size_t)c * (KK * HH);

        if (s <= -(smM[i] + MARGIN)) {
            // truly silent: outputs must be zero
            if (smCls[i] != 1) {     // memory not already zeros
                float4 z = make_float4(0.f, 0.f, 0.f, 0.f);
                float4* o4 = reinterpret_cast<float4*>(orow);
                float4* s4 = reinterpret_cast<float4*>(srow);
#pragma unroll
                for (int it = 0; it < (KK * HH / 4) / 32; ++it) {
                    o4[it * 32 + lane] = z;
                    if (write_spikes) s4[it * 32 + lane] = z;
                }
            }
            s += smS[i];
            ++i;
            continue;
        }

        // active off-chain: memory holds the g_in-trajectory (invariant).
        float endv;
        bool merged = dual_patch(x + (size_t)c * HH, t, smIn[i], s,
                                 orow, srow, write_spikes, &endv);
        if (merged) {
            // identical to the g_in-trajectory afterward -> its exact end:
            s = smBad[i] ? smEndv[i] : smE[i];
        } else {
            s = endv;
        }
        ++i;
    }
}

extern "C" void kernel_launch(void* const* d_in, const int* in_sizes, int n_in,
                              void* d_out, int out_size) {
    const float* x  = (const float*)d_in[0];   // (B, S, H) f32
    const float* th = (const float*)d_in[1];   // (K,) f32
    float* outs = (float*)d_out;

    const long long N = (long long)BB * SS * KK * HH;   // 16777216
    int write_spikes = ((long long)out_size >= 2 * N) ? 1 : 0;
    float* spikes = outs + N;

    lif_spec_kernel<<<NCHUNK / (CPW * WPB), WPB * 32>>>(x, th, outs, spikes,
                                                        write_spikes);
    lif_state_kernel<<<BB, 32>>>();
    lif_verify_kernel<<<(NCHUNK * 32) / 256, 256>>>(x, th, outs, spikes,
                                                    write_spikes);
    lif_repair_kernel<<<BB, 32>>>(x, th, outs, spikes, write_spikes);
}